// round 1
// baseline (speedup 1.0000x reference)
#include <cuda_runtime.h>

// ---------------- scratch (no allocations allowed) ----------------
__device__ float g_feat[16384 * 192];  // fusion features per (row, half)
__device__ float g_ce[8192 * 576];     // ce = concat(e1, e2), == (16384 x 288) row-major
__device__ float g_h[8192 * 288];      // hidden after cl_W1 + bn + relu

__device__ __forceinline__ float lrelu_f(float v) { return v >= 0.f ? v : 0.1f * v; }

// =====================================================================
// K1: per (row, half) fusion features.
//   - two stacked 3-tap conv1d + lrelu on the 3 segments (arm, x86, bert)
//   - ker[9] = lrelu(bert . de_W^T + de_b)
//   - m = lrelu(a (outer) b) = 0.1 a*b + 0.9 a+*b+ + 0.9 a-*b-   (rank 3, exact)
//   - fe = lrelu(depthwise 3x3 conv(m))  computed via rank-9 factorization
//   - outputs [rowmean(96) ; colmean(96)] -> g_feat
// =====================================================================
__global__ __launch_bounds__(192) void k1_fusion(
    const float* __restrict__ x,
    const float* __restrict__ cw1, const float* __restrict__ cb1,
    const float* __restrict__ cw2, const float* __restrict__ cb2,
    const float* __restrict__ cw3, const float* __restrict__ cb3,
    const float* __restrict__ cw4, const float* __restrict__ cb4,
    const float* __restrict__ cw5, const float* __restrict__ cb5,
    const float* __restrict__ cw6, const float* __restrict__ cb6,
    const float* __restrict__ de_W, const float* __restrict__ de_b,
    float* __restrict__ gfeat)
{
    int r = blockIdx.x;
    int h = blockIdx.y;
    int t = threadIdx.x;
    int warp = t >> 5, lane = t & 31;

    __shared__ float sin_[288];
    __shared__ float t1[288];
    __shared__ float abuf[3][96];   // arm, x86, bert (post 2nd conv + lrelu)
    __shared__ float upad[3][98];   // padded rank-3 row factors (from arm)
    __shared__ float vpad[3][98];   // padded rank-3 col factors (from x86)
    __shared__ float wv[9][96];     // w_{t,di}[j] = sum_dj ker[di,dj] * vpad[t][j+dj]
    __shared__ float kersh[9];
    __shared__ float rowsum[96];
    __shared__ float colsum[96];

    const float* xr = x + (size_t)r * 576 + (size_t)h * 288;
    for (int i = t; i < 288; i += 192) sin_[i] = xr[i];
    if (t < 96) { rowsum[t] = 0.f; colsum[t] = 0.f; }
    __syncthreads();

    // conv layer 1 (cross-correlation, pad 1)
    for (int i = t; i < 288; i += 192) {
        int s = i / 96, l = i % 96;
        const float* cw = (s == 0) ? cw1 : (s == 1) ? cw2 : cw3;
        float cb = ((s == 0) ? cb1 : (s == 1) ? cb2 : cb3)[0];
        float left  = (l > 0)  ? sin_[i - 1] : 0.f;
        float right = (l < 95) ? sin_[i + 1] : 0.f;
        t1[i] = lrelu_f(left * cw[0] + sin_[i] * cw[1] + right * cw[2] + cb);
    }
    __syncthreads();
    // conv layer 2
    for (int i = t; i < 288; i += 192) {
        int s = i / 96, l = i % 96;
        const float* cw = (s == 0) ? cw4 : (s == 1) ? cw5 : cw6;
        float cb = ((s == 0) ? cb4 : (s == 1) ? cb5 : cb6)[0];
        float left  = (l > 0)  ? t1[i - 1] : 0.f;
        float right = (l < 95) ? t1[i + 1] : 0.f;
        abuf[s][l] = lrelu_f(left * cw[0] + t1[i] * cw[1] + right * cw[2] + cb);
    }
    __syncthreads();

    // ker[9] = lrelu(bert . de_W[k] + de_b[k]); 6 warps cover 9 k's
    for (int k = warp; k < 9; k += 6) {
        const float* dw = de_W + k * 96;
        float p = abuf[2][lane]        * dw[lane]
                + abuf[2][lane + 32]   * dw[lane + 32]
                + abuf[2][lane + 64]   * dw[lane + 64];
        #pragma unroll
        for (int o = 16; o; o >>= 1) p += __shfl_xor_sync(0xffffffffu, p, o);
        if (lane == 0) kersh[k] = lrelu_f(p + de_b[k]);
    }

    // padded rank-3 factors: m = sum_t upad_t (outer) vpad_t
    if (t < 96) {
        float a = abuf[0][t], b = abuf[1][t];
        upad[0][t + 1] = 0.1f * a;
        upad[1][t + 1] = 0.9f * fmaxf(a, 0.f);
        upad[2][t + 1] = 0.9f * fminf(a, 0.f);
        vpad[0][t + 1] = b;
        vpad[1][t + 1] = fmaxf(b, 0.f);
        vpad[2][t + 1] = fminf(b, 0.f);
    } else if (t < 102) {
        int q = t - 96;
        int side = (q < 3) ? 0 : 97;
        upad[q % 3][side] = 0.f;
        vpad[q % 3][side] = 0.f;
    }
    __syncthreads();

    // wv[t*3+di][j] = sum_dj ker[di*3+dj] * vpad[t][j + dj]
    for (int idx = t; idx < 288; idx += 192) {
        int tt = idx / 96, j = idx % 96;
        #pragma unroll
        for (int di = 0; di < 3; di++) {
            wv[tt * 3 + di][j] = kersh[di * 3 + 0] * vpad[tt][j]
                               + kersh[di * 3 + 1] * vpad[tt][j + 1]
                               + kersh[di * 3 + 2] * vpad[tt][j + 2];
        }
    }
    __syncthreads();

    // main loop: thread owns column j; lanes of a warp share i (rowsum via shfl)
    int j = t % 96;
    int base = (t / 96) * 48;   // ihalf in {0,1}
    float w9[9];
    #pragma unroll
    for (int q = 0; q < 9; q++) w9[q] = wv[q][j];

    float u0a = upad[0][base],     u1a = upad[1][base],     u2a = upad[2][base];
    float u0b = upad[0][base + 1], u1b = upad[1][base + 1], u2b = upad[2][base + 1];
    float csum = 0.f;
    #pragma unroll 4
    for (int i = base; i < base + 48; i++) {
        float u0c = upad[0][i + 2], u1c = upad[1][i + 2], u2c = upad[2][i + 2];
        float z = u0a * w9[0] + u0b * w9[1] + u0c * w9[2]
                + u1a * w9[3] + u1b * w9[4] + u1c * w9[5]
                + u2a * w9[6] + u2b * w9[7] + u2c * w9[8];
        float fe = lrelu_f(z);
        csum += fe;
        float rs = fe;
        #pragma unroll
        for (int o = 16; o; o >>= 1) rs += __shfl_xor_sync(0xffffffffu, rs, o);
        if (lane == 0) atomicAdd(&rowsum[i], rs);
        u0a = u0b; u0b = u0c; u1a = u1b; u1b = u1c; u2a = u2b; u2b = u2c;
    }
    atomicAdd(&colsum[j], csum);
    __syncthreads();

    if (t < 96) {
        float* go = gfeat + ((size_t)r * 2 + h) * 192;
        go[t]      = rowsum[t] * (1.f / 96.f);
        go[96 + t] = colsum[t] * (1.f / 96.f);
    }
}

// =====================================================================
// Tiled SGEMM with fused bias + BN + (leaky)relu + optional residual.
// out[m][n] = act( BN( sum_k A[m][k]*W[n][k] + bias[n] ) ) (+ resid[m][n])
// BM=128, BN=64, BK=16, 256 threads, 8x4 micro-tile.
// Requires M % 128 == 0, K % 16 == 0; N guarded.
// =====================================================================
__global__ __launch_bounds__(256) void sgemm_bn(
    const float* __restrict__ A, int M, int K,
    const float* __restrict__ W, int N,
    const float* __restrict__ bias,
    const float* __restrict__ bg, const float* __restrict__ bbe,
    const float* __restrict__ bm, const float* __restrict__ bv,
    float slope,
    const float* __restrict__ resid,
    float* __restrict__ out)
{
    const int BM = 128, BN = 64, BK = 16;
    __shared__ float As[BK][BM + 4];
    __shared__ float Bs[BK][BN + 4];

    int tid = threadIdx.x;
    int m0 = blockIdx.x * BM;
    int n0 = blockIdx.y * BN;
    int ty = tid / 16;          // 0..15  -> rows ty*8 .. ty*8+7
    int tx = tid % 16;          // 0..15  -> cols tx*4 .. tx*4+3
    int lr = tid >> 2;          // 0..63
    int lc = (tid & 3) * 4;     // 0,4,8,12

    float acc[8][4];
    #pragma unroll
    for (int i = 0; i < 8; i++)
        #pragma unroll
        for (int jq = 0; jq < 4; jq++) acc[i][jq] = 0.f;

    for (int k0 = 0; k0 < K; k0 += BK) {
        float4 a0 = *(const float4*)&A[(size_t)(m0 + lr) * K + k0 + lc];
        float4 a1 = *(const float4*)&A[(size_t)(m0 + lr + 64) * K + k0 + lc];
        float4 b0 = make_float4(0.f, 0.f, 0.f, 0.f);
        if (n0 + lr < N) b0 = *(const float4*)&W[(size_t)(n0 + lr) * K + k0 + lc];
        __syncthreads();
        As[lc + 0][lr] = a0.x; As[lc + 1][lr] = a0.y; As[lc + 2][lr] = a0.z; As[lc + 3][lr] = a0.w;
        As[lc + 0][lr + 64] = a1.x; As[lc + 1][lr + 64] = a1.y; As[lc + 2][lr + 64] = a1.z; As[lc + 3][lr + 64] = a1.w;
        Bs[lc + 0][lr] = b0.x; Bs[lc + 1][lr] = b0.y; Bs[lc + 2][lr] = b0.z; Bs[lc + 3][lr] = b0.w;
        __syncthreads();
        #pragma unroll
        for (int k = 0; k < BK; k++) {
            float4 av0 = *(const float4*)&As[k][ty * 8];
            float4 av1 = *(const float4*)&As[k][ty * 8 + 4];
            float4 bvv = *(const float4*)&Bs[k][tx * 4];
            float am[8] = {av0.x, av0.y, av0.z, av0.w, av1.x, av1.y, av1.z, av1.w};
            float bn4[4] = {bvv.x, bvv.y, bvv.z, bvv.w};
            #pragma unroll
            for (int i = 0; i < 8; i++)
                #pragma unroll
                for (int jq = 0; jq < 4; jq++)
                    acc[i][jq] += am[i] * bn4[jq];
        }
    }

    #pragma unroll
    for (int jq = 0; jq < 4; jq++) {
        int n = n0 + tx * 4 + jq;
        if (n >= N) continue;
        float sc   = rsqrtf(bv[n] + 1e-5f) * bg[n];
        float bb   = bias[n];
        float mm   = bm[n];
        float bbeN = bbe[n];
        #pragma unroll
        for (int i = 0; i < 8; i++) {
            int m = m0 + ty * 8 + i;
            float y = acc[i][jq] + bb;
            float z = (y - mm) * sc + bbeN;
            float act = z >= 0.f ? z : slope * z;
            if (resid) act += resid[(size_t)m * N + n];
            out[(size_t)m * N + n] = act;
        }
    }
}

// =====================================================================
// K4: out[row][0:2] = h[row] . cl_W2^T + cl_b2 ; warp per row
// =====================================================================
__global__ __launch_bounds__(256) void k4_final(
    const float* __restrict__ W2, const float* __restrict__ b2,
    float* __restrict__ out)
{
    int warp = threadIdx.x >> 5, lane = threadIdx.x & 31;
    int row = blockIdx.x * 8 + warp;
    const float* hr = g_h + (size_t)row * 288;
    float a0 = 0.f, a1 = 0.f;
    #pragma unroll
    for (int q = 0; q < 9; q++) {
        float v = hr[q * 32 + lane];
        a0 += v * W2[q * 32 + lane];
        a1 += v * W2[288 + q * 32 + lane];
    }
    #pragma unroll
    for (int o = 16; o; o >>= 1) {
        a0 += __shfl_xor_sync(0xffffffffu, a0, o);
        a1 += __shfl_xor_sync(0xffffffffu, a1, o);
    }
    if (lane == 0) {
        out[row * 2 + 0] = a0 + b2[0];
        out[row * 2 + 1] = a1 + b2[1];
    }
}

// =====================================================================
extern "C" void kernel_launch(void* const* d_in, const int* in_sizes, int n_in,
                              void* d_out, int out_size)
{
    (void)in_sizes; (void)n_in; (void)out_size;
    const float* x     = (const float*)d_in[0];
    const float* cw1   = (const float*)d_in[1];
    const float* cb1   = (const float*)d_in[2];
    const float* cw2   = (const float*)d_in[3];
    const float* cb2   = (const float*)d_in[4];
    const float* cw3   = (const float*)d_in[5];
    const float* cb3   = (const float*)d_in[6];
    const float* cw4   = (const float*)d_in[7];
    const float* cb4   = (const float*)d_in[8];
    const float* cw5   = (const float*)d_in[9];
    const float* cb5   = (const float*)d_in[10];
    const float* cw6   = (const float*)d_in[11];
    const float* cb6   = (const float*)d_in[12];
    const float* de_W  = (const float*)d_in[13];
    const float* de_b  = (const float*)d_in[14];
    const float* rs_W  = (const float*)d_in[15];
    const float* rs_b  = (const float*)d_in[16];
    const float* rs_g  = (const float*)d_in[17];
    const float* rs_be = (const float*)d_in[18];
    const float* rs_m  = (const float*)d_in[19];
    const float* rs_v  = (const float*)d_in[20];
    const float* cl_W1 = (const float*)d_in[21];
    const float* cl_b1 = (const float*)d_in[22];
    const float* cl_g  = (const float*)d_in[23];
    const float* cl_be = (const float*)d_in[24];
    const float* cl_m  = (const float*)d_in[25];
    const float* cl_v  = (const float*)d_in[26];
    const float* cl_W2 = (const float*)d_in[27];
    const float* cl_b2 = (const float*)d_in[28];

    float *pfeat, *pce, *ph;
    cudaGetSymbolAddress((void**)&pfeat, g_feat);
    cudaGetSymbolAddress((void**)&pce,   g_ce);
    cudaGetSymbolAddress((void**)&ph,    g_h);

    // K1: fusion features per (row, half)
    k1_fusion<<<dim3(8192, 2), 192>>>(x, cw1, cb1, cw2, cb2, cw3, cb3,
                                      cw4, cb4, cw5, cb5, cw6, cb6,
                                      de_W, de_b, pfeat);

    // K2: resh GEMM (16384 x 192) @ (288 x 192)^T, +bias, BN, lrelu, +x residual -> ce
    sgemm_bn<<<dim3(16384 / 128, (288 + 63) / 64), 256>>>(
        pfeat, 16384, 192, rs_W, 288,
        rs_b, rs_g, rs_be, rs_m, rs_v, 0.1f, x, pce);

    // K3: cl GEMM (8192 x 576) @ (288 x 576)^T, +bias, BN, relu -> h
    sgemm_bn<<<dim3(8192 / 128, (288 + 63) / 64), 256>>>(
        pce, 8192, 576, cl_W1, 288,
        cl_b1, cl_g, cl_be, cl_m, cl_v, 0.0f, nullptr, ph);

    // K4: final 288 -> 2
    k4_final<<<8192 / 8, 256>>>(cl_W2, cl_b2, (float*)d_out);
}

// round 2
// speedup vs baseline: 1.1262x; 1.1262x over previous
#include <cuda_runtime.h>

typedef unsigned long long ull;

// ---------------- packed f32x2 helpers (sm_103a) ----------------
__device__ __forceinline__ ull f2mul(ull a, ull b) {
    ull d; asm("mul.rn.f32x2 %0,%1,%2;" : "=l"(d) : "l"(a), "l"(b)); return d;
}
__device__ __forceinline__ ull f2fma(ull a, ull b, ull c) {
    ull d; asm("fma.rn.f32x2 %0,%1,%2,%3;" : "=l"(d) : "l"(a), "l"(b), "l"(c)); return d;
}
__device__ __forceinline__ void f2unpack(ull v, float& lo, float& hi) {
    asm("mov.b64 {%0,%1},%2;" : "=f"(lo), "=f"(hi) : "l"(v));
}

// ---------------- scratch (no allocations allowed) ----------------
__device__ float g_feat[16384 * 192];  // fusion features per (row, half)
__device__ float g_ce[8192 * 576];     // ce = concat(e1, e2) == (16384 x 288) row-major
__device__ float g_h[8192 * 288];      // hidden after cl_W1 + bn + relu

__device__ __forceinline__ float lrelu_f(float v) { return v >= 0.f ? v : 0.1f * v; }

// =====================================================================
// K1: per (row, half) fusion features.
//   m = lrelu(a (outer) b) = 0.1 a*b + 0.9 a+*b+ + 0.9 a-*b-   (rank 3, exact)
//   fe = lrelu(depthwise 3x3 conv(m)) via rank-9 factorization;
//   main loop: 12x4 register tile per thread, f32x2-packed column pairs,
//   row-partials staged to smem (conflict-free), colsum via end atomics.
// =====================================================================
__global__ __launch_bounds__(192) void k1_fusion(
    const float* __restrict__ x,
    const float* __restrict__ cw1, const float* __restrict__ cb1,
    const float* __restrict__ cw2, const float* __restrict__ cb2,
    const float* __restrict__ cw3, const float* __restrict__ cb3,
    const float* __restrict__ cw4, const float* __restrict__ cb4,
    const float* __restrict__ cw5, const float* __restrict__ cb5,
    const float* __restrict__ cw6, const float* __restrict__ cb6,
    const float* __restrict__ de_W, const float* __restrict__ de_b,
    float* __restrict__ gfeat)
{
    int r = blockIdx.x;
    int h = blockIdx.y;
    int t = threadIdx.x;
    int warp = t >> 5, lane = t & 31;

    __shared__ float sin_[288];
    __shared__ float t1[288];
    __shared__ float abuf[3][96];                 // arm, x86, bert after conv stack
    __shared__ __align__(16) float vpad[3][98];   // padded col factors
    __shared__ __align__(16) float u2[3][196];    // DUPLICATED padded row factors: u2[t][2p]=u2[t][2p+1]
    __shared__ __align__(16) float wv[9][96];     // w_{t,di}[j]
    __shared__ float kersh[9];
    __shared__ float colsum[96];
    __shared__ __align__(16) float stage[96 * 25]; // row partial sums: stage[i*25+tx]

    const float* xr = x + (size_t)r * 576 + (size_t)h * 288;
    for (int i = t; i < 288; i += 192) sin_[i] = xr[i];
    __syncthreads();

    // conv layer 1 (cross-correlation, pad 1)
    for (int i = t; i < 288; i += 192) {
        int s = i / 96, l = i % 96;
        const float* cw = (s == 0) ? cw1 : (s == 1) ? cw2 : cw3;
        float cb = ((s == 0) ? cb1 : (s == 1) ? cb2 : cb3)[0];
        float left  = (l > 0)  ? sin_[i - 1] : 0.f;
        float right = (l < 95) ? sin_[i + 1] : 0.f;
        t1[i] = lrelu_f(left * cw[0] + sin_[i] * cw[1] + right * cw[2] + cb);
    }
    __syncthreads();
    // conv layer 2
    for (int i = t; i < 288; i += 192) {
        int s = i / 96, l = i % 96;
        const float* cw = (s == 0) ? cw4 : (s == 1) ? cw5 : cw6;
        float cb = ((s == 0) ? cb4 : (s == 1) ? cb5 : cb6)[0];
        float left  = (l > 0)  ? t1[i - 1] : 0.f;
        float right = (l < 95) ? t1[i + 1] : 0.f;
        abuf[s][l] = lrelu_f(left * cw[0] + t1[i] * cw[1] + right * cw[2] + cb);
    }
    __syncthreads();

    // ker[9] = lrelu(bert . de_W[k] + de_b[k])
    for (int k = warp; k < 9; k += 6) {
        const float* dw = de_W + k * 96;
        float p = abuf[2][lane]      * dw[lane]
                + abuf[2][lane + 32] * dw[lane + 32]
                + abuf[2][lane + 64] * dw[lane + 64];
        #pragma unroll
        for (int o = 16; o; o >>= 1) p += __shfl_xor_sync(0xffffffffu, p, o);
        if (lane == 0) kersh[k] = lrelu_f(p + de_b[k]);
    }

    // rank-3 factors (u duplicated for packed loads), padded borders zero
    if (t < 96) {
        float a = abuf[0][t], b = abuf[1][t];
        float p0 = 0.1f * a;
        float p1 = 0.9f * fmaxf(a, 0.f);
        float p2 = 0.9f * fminf(a, 0.f);
        u2[0][2 * (t + 1)] = p0; u2[0][2 * (t + 1) + 1] = p0;
        u2[1][2 * (t + 1)] = p1; u2[1][2 * (t + 1) + 1] = p1;
        u2[2][2 * (t + 1)] = p2; u2[2][2 * (t + 1) + 1] = p2;
        vpad[0][t + 1] = b;
        vpad[1][t + 1] = fmaxf(b, 0.f);
        vpad[2][t + 1] = fminf(b, 0.f);
        colsum[t] = 0.f;
    } else if (t < 102) {
        int q = t - 96;             // 6 border combos: (tt, side)
        int tt = q % 3;
        int side = (q < 3) ? 0 : 97;
        vpad[tt][side] = 0.f;
        u2[tt][2 * side] = 0.f;
        u2[tt][2 * side + 1] = 0.f;
    }
    __syncthreads();

    // wv[tt*3+di][j] = sum_dj ker[di*3+dj] * vpad[tt][j + dj]
    for (int idx = t; idx < 288; idx += 192) {
        int tt = idx / 96, j = idx % 96;
        #pragma unroll
        for (int di = 0; di < 3; di++) {
            wv[tt * 3 + di][j] = kersh[di * 3 + 0] * vpad[tt][j]
                               + kersh[di * 3 + 1] * vpad[tt][j + 1]
                               + kersh[di * 3 + 2] * vpad[tt][j + 2];
        }
    }
    __syncthreads();

    // ---- main loop: thread tile = 12 rows x 4 cols (2 packed column pairs)
    int ty = t & 7;          // 0..7  -> rows ty*12..ty*12+11
    int tx = t >> 3;         // 0..23 -> cols tx*4..tx*4+3
    int i0 = ty * 12, j0 = tx * 4;

    ull w20[9], w21[9];
    #pragma unroll
    for (int q = 0; q < 9; q++) {
        w20[q] = *(const ull*)&wv[q][j0];
        w21[q] = *(const ull*)&wv[q][j0 + 2];
    }

    ull ua0 = *(const ull*)&u2[0][2 * i0];
    ull ua1 = *(const ull*)&u2[1][2 * i0];
    ull ua2 = *(const ull*)&u2[2][2 * i0];
    ull ub0 = *(const ull*)&u2[0][2 * i0 + 2];
    ull ub1 = *(const ull*)&u2[1][2 * i0 + 2];
    ull ub2 = *(const ull*)&u2[2][2 * i0 + 2];

    float cs0 = 0.f, cs1 = 0.f, cs2 = 0.f, cs3 = 0.f;
    #pragma unroll
    for (int s = 0; s < 12; s++) {
        int p2 = 2 * (i0 + s + 2);
        ull uc0 = *(const ull*)&u2[0][p2];
        ull uc1 = *(const ull*)&u2[1][p2];
        ull uc2 = *(const ull*)&u2[2][p2];

        ull zA = f2mul(ua0, w20[0]);
        zA = f2fma(ub0, w20[1], zA); zA = f2fma(uc0, w20[2], zA);
        zA = f2fma(ua1, w20[3], zA); zA = f2fma(ub1, w20[4], zA); zA = f2fma(uc1, w20[5], zA);
        zA = f2fma(ua2, w20[6], zA); zA = f2fma(ub2, w20[7], zA); zA = f2fma(uc2, w20[8], zA);

        ull zB = f2mul(ua0, w21[0]);
        zB = f2fma(ub0, w21[1], zB); zB = f2fma(uc0, w21[2], zB);
        zB = f2fma(ua1, w21[3], zB); zB = f2fma(ub1, w21[4], zB); zB = f2fma(uc1, w21[5], zB);
        zB = f2fma(ua2, w21[6], zB); zB = f2fma(ub2, w21[7], zB); zB = f2fma(uc2, w21[8], zB);

        float z0, z1, z2, z3;
        f2unpack(zA, z0, z1);
        f2unpack(zB, z2, z3);
        float f0 = fmaxf(z0, 0.f) + 0.1f * fminf(z0, 0.f);
        float f1 = fmaxf(z1, 0.f) + 0.1f * fminf(z1, 0.f);
        float f2v = fmaxf(z2, 0.f) + 0.1f * fminf(z2, 0.f);
        float f3 = fmaxf(z3, 0.f) + 0.1f * fminf(z3, 0.f);
        cs0 += f0; cs1 += f1; cs2 += f2v; cs3 += f3;
        stage[(i0 + s) * 25 + tx] = (f0 + f1) + (f2v + f3);

        ua0 = ub0; ub0 = uc0;
        ua1 = ub1; ub1 = uc1;
        ua2 = ub2; ub2 = uc2;
    }
    atomicAdd(&colsum[j0 + 0], cs0);
    atomicAdd(&colsum[j0 + 1], cs1);
    atomicAdd(&colsum[j0 + 2], cs2);
    atomicAdd(&colsum[j0 + 3], cs3);
    __syncthreads();

    float* go = gfeat + ((size_t)r * 2 + h) * 192;
    if (t < 96) {
        float acc = 0.f;
        #pragma unroll
        for (int q = 0; q < 24; q++) acc += stage[t * 25 + q];
        go[t] = acc * (1.f / 96.f);
    } else {
        int j = t - 96;
        go[96 + j] = colsum[j] * (1.f / 96.f);
    }
}

// =====================================================================
// Packed-f32x2 SGEMM with fused bias + BN + (leaky)relu + optional residual.
// out[m][n] = act( BN( sum_k A[m][k]*W[n][k] + bias[n] ) ) (+ resid[m][n])
// BM=64, BN=96, BK=16, 128 threads, 8x6 micro-tile, accumulators packed
// over M (row pairs). B stored DUPLICATED in smem so {b,b} is one LDS.64.
// Requires M%64==0, K%16==0, N%96==0.
// =====================================================================
__global__ __launch_bounds__(128) void sgemm_bn(
    const float* __restrict__ A, int M, int K,
    const float* __restrict__ W, int N,
    const float* __restrict__ bias,
    const float* __restrict__ bg, const float* __restrict__ bbe,
    const float* __restrict__ bm, const float* __restrict__ bv,
    float slope,
    const float* __restrict__ resid,
    float* __restrict__ out)
{
    __shared__ __align__(16) float As[16][68];     // [k][m], padded
    __shared__ __align__(16) float Bs2[16][192];   // [k][2n] duplicated

    int tid = threadIdx.x;
    int m0 = blockIdx.x * 64;
    int n0 = blockIdx.y * 96;
    int ty = tid >> 4;       // 0..7  -> rows ty*8..ty*8+7 (4 packed pairs)
    int tx = tid & 15;       // 0..15 -> cols tx + 16*c, c in 0..5

    ull acc[4][6];
    #pragma unroll
    for (int r2 = 0; r2 < 4; r2++)
        #pragma unroll
        for (int c = 0; c < 6; c++) acc[r2][c] = 0ull;

    for (int k0 = 0; k0 < K; k0 += 16) {
        __syncthreads();
        // fill A: 64x16 = 256 float4 over 128 threads
        #pragma unroll
        for (int q = 0; q < 2; q++) {
            int idx = tid + q * 128;
            int rr = idx >> 2, cc = (idx & 3) * 4;
            float4 a4 = *(const float4*)&A[(size_t)(m0 + rr) * K + k0 + cc];
            As[cc + 0][rr] = a4.x; As[cc + 1][rr] = a4.y;
            As[cc + 2][rr] = a4.z; As[cc + 3][rr] = a4.w;
        }
        // fill B duplicated: 96x16 = 384 float4 over 128 threads
        #pragma unroll
        for (int q = 0; q < 3; q++) {
            int idx = tid + q * 128;
            int rr = idx >> 2, cc = (idx & 3) * 4;
            float4 w4 = *(const float4*)&W[(size_t)(n0 + rr) * K + k0 + cc];
            *(float2*)&Bs2[cc + 0][2 * rr] = make_float2(w4.x, w4.x);
            *(float2*)&Bs2[cc + 1][2 * rr] = make_float2(w4.y, w4.y);
            *(float2*)&Bs2[cc + 2][2 * rr] = make_float2(w4.z, w4.z);
            *(float2*)&Bs2[cc + 3][2 * rr] = make_float2(w4.w, w4.w);
        }
        __syncthreads();

        #pragma unroll
        for (int kk = 0; kk < 16; kk++) {
            ull a2[4], b2[6];
            #pragma unroll
            for (int r2 = 0; r2 < 4; r2++)
                a2[r2] = *(const ull*)&As[kk][ty * 8 + 2 * r2];
            #pragma unroll
            for (int c = 0; c < 6; c++)
                b2[c] = *(const ull*)&Bs2[kk][2 * tx + 32 * c];
            #pragma unroll
            for (int r2 = 0; r2 < 4; r2++)
                #pragma unroll
                for (int c = 0; c < 6; c++)
                    acc[r2][c] = f2fma(a2[r2], b2[c], acc[r2][c]);
        }
    }

    #pragma unroll
    for (int c = 0; c < 6; c++) {
        int n = n0 + tx + 16 * c;
        float sc   = rsqrtf(bv[n] + 1e-5f) * bg[n];
        float bb   = bias[n];
        float mm   = bm[n];
        float beN  = bbe[n];
        #pragma unroll
        for (int r2 = 0; r2 < 4; r2++) {
            float zlo, zhi;
            f2unpack(acc[r2][c], zlo, zhi);
            int m = m0 + ty * 8 + 2 * r2;
            float v0 = (zlo + bb - mm) * sc + beN;
            float v1 = (zhi + bb - mm) * sc + beN;
            float a0 = v0 >= 0.f ? v0 : slope * v0;
            float a1 = v1 >= 0.f ? v1 : slope * v1;
            if (resid) {
                a0 += resid[(size_t)m * N + n];
                a1 += resid[(size_t)(m + 1) * N + n];
            }
            out[(size_t)m * N + n] = a0;
            out[(size_t)(m + 1) * N + n] = a1;
        }
    }
}

// =====================================================================
// K4: out[row][0:2] = h[row] . cl_W2^T + cl_b2 ; warp per row
// =====================================================================
__global__ __launch_bounds__(256) void k4_final(
    const float* __restrict__ W2, const float* __restrict__ b2,
    float* __restrict__ out)
{
    int warp = threadIdx.x >> 5, lane = threadIdx.x & 31;
    int row = blockIdx.x * 8 + warp;
    const float* hr = g_h + (size_t)row * 288;
    float a0 = 0.f, a1 = 0.f;
    #pragma unroll
    for (int q = 0; q < 9; q++) {
        float v = hr[q * 32 + lane];
        a0 += v * W2[q * 32 + lane];
        a1 += v * W2[288 + q * 32 + lane];
    }
    #pragma unroll
    for (int o = 16; o; o >>= 1) {
        a0 += __shfl_xor_sync(0xffffffffu, a0, o);
        a1 += __shfl_xor_sync(0xffffffffu, a1, o);
    }
    if (lane == 0) {
        out[row * 2 + 0] = a0 + b2[0];
        out[row * 2 + 1] = a1 + b2[1];
    }
}

// =====================================================================
extern "C" void kernel_launch(void* const* d_in, const int* in_sizes, int n_in,
                              void* d_out, int out_size)
{
    (void)in_sizes; (void)n_in; (void)out_size;
    const float* x     = (const float*)d_in[0];
    const float* cw1   = (const float*)d_in[1];
    const float* cb1   = (const float*)d_in[2];
    const float* cw2   = (const float*)d_in[3];
    const float* cb2   = (const float*)d_in[4];
    const float* cw3   = (const float*)d_in[5];
    const float* cb3   = (const float*)d_in[6];
    const float* cw4   = (const float*)d_in[7];
    const float* cb4   = (const float*)d_in[8];
    const float* cw5   = (const float*)d_in[9];
    const float* cb5   = (const float*)d_in[10];
    const float* cw6   = (const float*)d_in[11];
    const float* cb6   = (const float*)d_in[12];
    const float* de_W  = (const float*)d_in[13];
    const float* de_b  = (const float*)d_in[14];
    const float* rs_W  = (const float*)d_in[15];
    const float* rs_b  = (const float*)d_in[16];
    const float* rs_g  = (const float*)d_in[17];
    const float* rs_be = (const float*)d_in[18];
    const float* rs_m  = (const float*)d_in[19];
    const float* rs_v  = (const float*)d_in[20];
    const float* cl_W1 = (const float*)d_in[21];
    const float* cl_b1 = (const float*)d_in[22];
    const float* cl_g  = (const float*)d_in[23];
    const float* cl_be = (const float*)d_in[24];
    const float* cl_m  = (const float*)d_in[25];
    const float* cl_v  = (const float*)d_in[26];
    const float* cl_W2 = (const float*)d_in[27];
    const float* cl_b2 = (const float*)d_in[28];

    float *pfeat, *pce, *ph;
    cudaGetSymbolAddress((void**)&pfeat, g_feat);
    cudaGetSymbolAddress((void**)&pce,   g_ce);
    cudaGetSymbolAddress((void**)&ph,    g_h);

    // K1: fusion features per (row, half)
    k1_fusion<<<dim3(8192, 2), 192>>>(x, cw1, cb1, cw2, cb2, cw3, cb3,
                                      cw4, cb4, cw5, cb5, cw6, cb6,
                                      de_W, de_b, pfeat);

    // K2: resh GEMM (16384 x 192) @ (288 x 192)^T, +bias, BN, lrelu, +x residual -> ce
    sgemm_bn<<<dim3(16384 / 64, 3), 128>>>(
        pfeat, 16384, 192, rs_W, 288,
        rs_b, rs_g, rs_be, rs_m, rs_v, 0.1f, x, pce);

    // K3: cl GEMM (8192 x 576) @ (288 x 576)^T, +bias, BN, relu -> h
    sgemm_bn<<<dim3(8192 / 64, 3), 128>>>(
        pce, 8192, 576, cl_W1, 288,
        cl_b1, cl_g, cl_be, cl_m, cl_v, 0.0f, nullptr, ph);

    // K4: final 288 -> 2
    k4_final<<<8192 / 8, 256>>>(cl_W2, cl_b2, (float*)d_out);
}